// round 14
// baseline (speedup 1.0000x reference)
#include <cuda_runtime.h>
#include <cuda_bf16.h>
#include <math.h>

#define BATCH 8
#define TLEN 512
#define NLEN 1024
#define DIM 1024
#define HEADS 16
#define HDIM 64

typedef unsigned long long u64;
typedef unsigned int u32;

// ---------------- mma.sync helpers ----------------
__device__ __forceinline__ u32 smem_u32(const void* p) {
    u32 a;
    asm("{ .reg .u64 t; cvta.to.shared.u64 t, %1; cvt.u32.u64 %0, t; }"
        : "=r"(a) : "l"(p));
    return a;
}
__device__ __forceinline__ void ldsm4(u32& r0, u32& r1, u32& r2, u32& r3, u32 addr) {
    asm volatile("ldmatrix.sync.aligned.m8n8.x4.shared.b16 {%0,%1,%2,%3}, [%4];"
                 : "=r"(r0), "=r"(r1), "=r"(r2), "=r"(r3) : "r"(addr));
}
__device__ __forceinline__ void mma_bf16(float* c, const u32* a, const u32* b) {
    asm volatile(
        "mma.sync.aligned.m16n8k16.row.col.f32.bf16.bf16.f32 "
        "{%0,%1,%2,%3}, {%4,%5,%6,%7}, {%8,%9}, {%0,%1,%2,%3};"
        : "+f"(c[0]), "+f"(c[1]), "+f"(c[2]), "+f"(c[3])
        : "r"(a[0]), "r"(a[1]), "r"(a[2]), "r"(a[3]), "r"(b[0]), "r"(b[1]));
}
__device__ __forceinline__ void cpa(u32 s, const void* g) {
    asm volatile("cp.async.cg.shared.global [%0], [%1], 16;" :: "r"(s), "l"(g));
}
__device__ __forceinline__ u32 pack_bf16(float lo, float hi) {
    u32 r;
    asm("cvt.rn.bf16x2.f32 %0, %1, %2;" : "=r"(r) : "f"(hi), "f"(lo));
    return r;
}
__device__ __forceinline__ u32 pack_resid(u32 hp, float lo, float hi) {
    float rl = lo - __bfloat162float(__ushort_as_bfloat16((unsigned short)(hp & 0xFFFFu)));
    float rh = hi - __bfloat162float(__ushort_as_bfloat16((unsigned short)(hp >> 16)));
    return pack_bf16(rl, rh);
}

// ---------------- scratch (no cudaMalloc) ----------------
__device__ float g_Qbuf[BATCH * TLEN * DIM];
__device__ float g_Kbuf[BATCH * NLEN * DIM];

__device__ __nv_bfloat16 g_th[BATCH * TLEN * DIM];
__device__ __nv_bfloat16 g_tl[BATCH * TLEN * DIM];
__device__ __nv_bfloat16 g_fh[BATCH * NLEN * DIM];
__device__ __nv_bfloat16 g_fl[BATCH * NLEN * DIM];
__device__ __nv_bfloat16 g_ah[BATCH * TLEN * DIM];
__device__ __nv_bfloat16 g_al[BATCH * TLEN * DIM];
__device__ __nv_bfloat16 g_qh[BATCH * TLEN * DIM];
__device__ __nv_bfloat16 g_ql[BATCH * TLEN * DIM];
__device__ __nv_bfloat16 g_kh[BATCH * NLEN * DIM];
__device__ __nv_bfloat16 g_kl[BATCH * NLEN * DIM];
__device__ __nv_bfloat16 g_vth[BATCH * NLEN * DIM];
__device__ __nv_bfloat16 g_vtl[BATCH * NLEN * DIM];
__device__ __nv_bfloat16 g_wqh[DIM * DIM];
__device__ __nv_bfloat16 g_wql[DIM * DIM];
__device__ __nv_bfloat16 g_wkh[DIM * DIM];
__device__ __nv_bfloat16 g_wkl[DIM * DIM];
__device__ __nv_bfloat16 g_woh[DIM * DIM];
__device__ __nv_bfloat16 g_wol[DIM * DIM];

// ---------------------------------------------------------------------------
// Split fp32 -> bf16 hi/lo (single tensor)
// ---------------------------------------------------------------------------
__global__ void convert_split_kernel(const float* __restrict__ in,
                                     __nv_bfloat16* __restrict__ hi,
                                     __nv_bfloat16* __restrict__ lo) {
    int i = blockIdx.x * blockDim.x + threadIdx.x;
    float4 v = ((const float4*)in)[i];
    __nv_bfloat16 h0 = __float2bfloat16(v.x);
    __nv_bfloat16 h1 = __float2bfloat16(v.y);
    __nv_bfloat16 h2 = __float2bfloat16(v.z);
    __nv_bfloat16 h3 = __float2bfloat16(v.w);
    __nv_bfloat16 l0 = __float2bfloat16(v.x - __bfloat162float(h0));
    __nv_bfloat16 l1 = __float2bfloat16(v.y - __bfloat162float(h1));
    __nv_bfloat16 l2 = __float2bfloat16(v.z - __bfloat162float(h2));
    __nv_bfloat16 l3 = __float2bfloat16(v.w - __bfloat162float(h3));
    __nv_bfloat162* H = (__nv_bfloat162*)hi;
    __nv_bfloat162* L = (__nv_bfloat162*)lo;
    H[2 * i]     = __nv_bfloat162(h0, h1);
    H[2 * i + 1] = __nv_bfloat162(h2, h3);
    L[2 * i]     = __nv_bfloat162(l0, l1);
    L[2 * i + 1] = __nv_bfloat162(l2, l3);
}

// batched weight split
__global__ void convert_split3_kernel(const float* __restrict__ w0,
                                      const float* __restrict__ w1,
                                      const float* __restrict__ w2,
                                      __nv_bfloat16* __restrict__ h0p,
                                      __nv_bfloat16* __restrict__ l0p,
                                      __nv_bfloat16* __restrict__ h1p,
                                      __nv_bfloat16* __restrict__ l1p,
                                      __nv_bfloat16* __restrict__ h2p,
                                      __nv_bfloat16* __restrict__ l2p) {
    int z = blockIdx.y;
    const float* in = z == 0 ? w0 : (z == 1 ? w1 : w2);
    __nv_bfloat16* hi = z == 0 ? h0p : (z == 1 ? h1p : h2p);
    __nv_bfloat16* lo = z == 0 ? l0p : (z == 1 ? l1p : l2p);
    int i = blockIdx.x * blockDim.x + threadIdx.x;
    float4 v = ((const float4*)in)[i];
    __nv_bfloat16 a0 = __float2bfloat16(v.x);
    __nv_bfloat16 a1 = __float2bfloat16(v.y);
    __nv_bfloat16 a2 = __float2bfloat16(v.z);
    __nv_bfloat16 a3 = __float2bfloat16(v.w);
    __nv_bfloat16 b0 = __float2bfloat16(v.x - __bfloat162float(a0));
    __nv_bfloat16 b1 = __float2bfloat16(v.y - __bfloat162float(a1));
    __nv_bfloat16 b2 = __float2bfloat16(v.z - __bfloat162float(a2));
    __nv_bfloat16 b3 = __float2bfloat16(v.w - __bfloat162float(a3));
    __nv_bfloat162* H = (__nv_bfloat162*)hi;
    __nv_bfloat162* L = (__nv_bfloat162*)lo;
    H[2 * i]     = __nv_bfloat162(a0, a1);
    H[2 * i + 1] = __nv_bfloat162(a2, a3);
    L[2 * i]     = __nv_bfloat162(b0, b1);
    L[2 * i + 1] = __nv_bfloat162(b2, b3);
}

// ---------------------------------------------------------------------------
// RMSNorm -> scaled bf16 hi/lo split (single input)
// ---------------------------------------------------------------------------
__global__ void rmsnorm_split_kernel(const float* __restrict__ in,
                                     const float* __restrict__ g,
                                     float scale,
                                     __nv_bfloat16* __restrict__ hi,
                                     __nv_bfloat16* __restrict__ lo) {
    int row = blockIdx.x;
    int tid = threadIdx.x;
    const float4* x4 = (const float4*)(in + (size_t)row * DIM);
    float4 v = x4[tid];
    float s = v.x * v.x + v.y * v.y + v.z * v.z + v.w * v.w;
    #pragma unroll
    for (int o = 16; o > 0; o >>= 1) s += __shfl_xor_sync(0xffffffffu, s, o);
    __shared__ float ws[8];
    __shared__ float rsh;
    if ((tid & 31) == 0) ws[tid >> 5] = s;
    __syncthreads();
    if (tid == 0) {
        float t = 0.f;
        #pragma unroll
        for (int i = 0; i < 8; i++) t += ws[i];
        rsh = rsqrtf(t * (1.0f / DIM) + 1e-6f);
    }
    __syncthreads();
    float r = rsh * scale;
    float4 gv = ((const float4*)g)[tid];
    float ox = v.x * r * gv.x, oy = v.y * r * gv.y;
    float oz = v.z * r * gv.z, ow = v.w * r * gv.w;
    __nv_bfloat16 h0 = __float2bfloat16(ox);
    __nv_bfloat16 h1 = __float2bfloat16(oy);
    __nv_bfloat16 h2 = __float2bfloat16(oz);
    __nv_bfloat16 h3 = __float2bfloat16(ow);
    __nv_bfloat16 e0 = __float2bfloat16(ox - __bfloat162float(h0));
    __nv_bfloat16 e1 = __float2bfloat16(oy - __bfloat162float(h1));
    __nv_bfloat16 e2 = __float2bfloat16(oz - __bfloat162float(h2));
    __nv_bfloat16 e3 = __float2bfloat16(ow - __bfloat162float(h3));
    size_t base = (size_t)row * DIM + tid * 4;
    __nv_bfloat162* H = (__nv_bfloat162*)(hi + base);
    __nv_bfloat162* L = (__nv_bfloat162*)(lo + base);
    H[0] = __nv_bfloat162(h0, h1); H[1] = __nv_bfloat162(h2, h3);
    L[0] = __nv_bfloat162(e0, e1); L[1] = __nv_bfloat162(e2, e3);
}

// Fused rmsnorm for Q (rows 0..mt-1) and K (rows mt..)
__global__ void rmsnorm_split2_kernel(const float* __restrict__ inQ,
                                      const float* __restrict__ gq,
                                      __nv_bfloat16* __restrict__ qh,
                                      __nv_bfloat16* __restrict__ ql,
                                      const float* __restrict__ inK,
                                      const float* __restrict__ gk,
                                      __nv_bfloat16* __restrict__ kh,
                                      __nv_bfloat16* __restrict__ kl,
                                      int mt) {
    int row = blockIdx.x;
    const float* in; const float* g; float scale;
    __nv_bfloat16 *hi, *lo;
    if (row < mt) {
        in = inQ; g = gq; scale = 0.125f; hi = qh; lo = ql;
    } else {
        in = inK; g = gk; scale = 1.0f; hi = kh; lo = kl; row -= mt;
    }
    int tid = threadIdx.x;
    const float4* x4 = (const float4*)(in + (size_t)row * DIM);
    float4 v = x4[tid];
    float s = v.x * v.x + v.y * v.y + v.z * v.z + v.w * v.w;
    #pragma unroll
    for (int o = 16; o > 0; o >>= 1) s += __shfl_xor_sync(0xffffffffu, s, o);
    __shared__ float ws[8];
    __shared__ float rsh;
    if ((tid & 31) == 0) ws[tid >> 5] = s;
    __syncthreads();
    if (tid == 0) {
        float t = 0.f;
        #pragma unroll
        for (int i = 0; i < 8; i++) t += ws[i];
        rsh = rsqrtf(t * (1.0f / DIM) + 1e-6f);
    }
    __syncthreads();
    float r = rsh * scale;
    float4 gv = ((const float4*)g)[tid];
    float ox = v.x * r * gv.x, oy = v.y * r * gv.y;
    float oz = v.z * r * gv.z, ow = v.w * r * gv.w;
    __nv_bfloat16 h0 = __float2bfloat16(ox);
    __nv_bfloat16 h1 = __float2bfloat16(oy);
    __nv_bfloat16 h2 = __float2bfloat16(oz);
    __nv_bfloat16 h3 = __float2bfloat16(ow);
    __nv_bfloat16 e0 = __float2bfloat16(ox - __bfloat162float(h0));
    __nv_bfloat16 e1 = __float2bfloat16(oy - __bfloat162float(h1));
    __nv_bfloat16 e2 = __float2bfloat16(oz - __bfloat162float(h2));
    __nv_bfloat16 e3 = __float2bfloat16(ow - __bfloat162float(h3));
    size_t base = (size_t)row * DIM + tid * 4;
    __nv_bfloat162* H = (__nv_bfloat162*)(hi + base);
    __nv_bfloat162* L = (__nv_bfloat162*)(lo + base);
    H[0] = __nv_bfloat162(h0, h1); H[1] = __nv_bfloat162(h2, h3);
    L[0] = __nv_bfloat162(e0, e1); L[1] = __nv_bfloat162(e2, e3);
}

// ---------------------------------------------------------------------------
// Transpose feats splits into V^T per (b,h)
// ---------------------------------------------------------------------------
__global__ void transpose_vt_kernel(const __nv_bfloat16* __restrict__ fh,
                                    const __nv_bfloat16* __restrict__ fl,
                                    __nv_bfloat16* __restrict__ vth,
                                    __nv_bfloat16* __restrict__ vtl) {
    __shared__ __nv_bfloat16 tH[32][34];
    __shared__ __nv_bfloat16 tL[32][34];
    int bh = blockIdx.z;
    int b = bh >> 4, h = bh & 15;
    int n0 = blockIdx.x * 32, d0 = blockIdx.y * 32;
    int tx = threadIdx.x, ty = threadIdx.y;
    #pragma unroll
    for (int i = 0; i < 4; i++) {
        int n = n0 + ty + i * 8;
        size_t src = (size_t)(b * NLEN + n) * DIM + h * HDIM + d0 + tx;
        tH[ty + i * 8][tx] = fh[src];
        tL[ty + i * 8][tx] = fl[src];
    }
    __syncthreads();
    #pragma unroll
    for (int i = 0; i < 4; i++) {
        int d = d0 + ty + i * 8;
        size_t dst = ((size_t)bh * HDIM + d) * NLEN + n0 + tx;
        vth[dst] = tH[tx][ty + i * 8];
        vtl[dst] = tL[tx][ty + i * 8];
    }
}

// ---------------------------------------------------------------------------
// Tensor-core GEMM body — 256 threads (8 warps, 4x2), warp tile 32x32,
// CTA tile 128x64, K-chunks 64, 2-stage cp.async, 96KB smem -> 2 CTAs/SM.
// Stage: Ah 16K | Al 16K | Wh 8K | Wl 8K = 48K.
// ---------------------------------------------------------------------------
#define MM_STAGE 49152
#define MM_SMEM (2 * MM_STAGE)
__device__ __forceinline__
void gemm_body(const __nv_bfloat16* Ah, const __nv_bfloat16* Al,
               const __nv_bfloat16* Wh, const __nv_bfloat16* Wl,
               const float* bias, float* C, int bm, int bn, char* smem) {
    const u32 sb = smem_u32(smem);
    int tid  = threadIdx.x;
    int wid  = tid >> 5, lane = tid & 31;
    int wm = (wid >> 1) * 32;    // 4 warp-rows of 32 -> 128
    int wn = (wid & 1) * 32;     // 2 warp-cols of 32 -> 64
    int ko = wid & 3;            // per-warp ks phase offset

    // A loaders: 128 rows x 128B, 256 threads
    int lrow = tid >> 1, lhalf = tid & 1;
    const char* gAh = (const char*)(Ah + (size_t)(bm + lrow) * DIM) + lhalf * 64;
    const char* gAl = (const char*)(Al + (size_t)(bm + lrow) * DIM) + lhalf * 64;
    // W loaders: 64 rows x 128B, 256 threads
    int wrow = tid >> 2, wq = tid & 3;
    const char* gWh = (const char*)(Wh + (size_t)(bn + wrow) * DIM) + wq * 32;
    const char* gWl = (const char*)(Wl + (size_t)(bn + wrow) * DIM) + wq * 32;

    float acc[2][4][4];
    #pragma unroll
    for (int mi = 0; mi < 2; mi++)
        #pragma unroll
        for (int n = 0; n < 4; n++)
            #pragma unroll
            for (int q = 0; q < 4; q++) acc[mi][n][q] = 0.f;

    int rA = wm + (lane & 15);
    int rW = wn + (lane & 15);
    u32 aRow = sb + (u32)rA * 128;
    u32 wRow = sb + 32768 + (u32)rW * 128;
    int uu  = lane >> 4;
    int sA7 = rA & 7, sW7 = rW & 7;

    auto issue_stage = [&](int stage, int c) {
        u32 st = sb + (u32)stage * MM_STAGE;
        u32 ab = st + (u32)lrow * 128;
        const char* pa = gAh + c * 128;
        const char* pb = gAl + c * 128;
        #pragma unroll
        for (int j = 0; j < 4; j++) {
            int u = lhalf * 4 + j;
            u32 sw = (u32)((u ^ (lrow & 7)) << 4);
            cpa(ab + sw,         pa + j * 16);
            cpa(ab + 16384 + sw, pb + j * 16);
        }
        u32 wb = st + 32768 + (u32)wrow * 128;
        const char* pc = gWh + c * 128;
        const char* pd = gWl + c * 128;
        #pragma unroll
        for (int j = 0; j < 2; j++) {
            int u = wq * 2 + j;
            u32 sw = (u32)((u ^ (wrow & 7)) << 4);
            cpa(wb + sw,        pc + j * 16);
            cpa(wb + 8192 + sw, pd + j * 16);
        }
        asm volatile("cp.async.commit_group;" ::: "memory");
    };

    issue_stage(0, 0);

    for (int c = 0; c < 16; c++) {
        int buf = c & 1;
        if (c + 1 < 16) {
            issue_stage(buf ^ 1, c + 1);
            asm volatile("cp.async.wait_group 1;" ::: "memory");
        } else {
            asm volatile("cp.async.wait_group 0;" ::: "memory");
        }
        __syncthreads();

        u32 stb = (u32)buf * MM_STAGE;
        #pragma unroll
        for (int ki = 0; ki < 4; ki++) {
            int ks = (ki + ko) & 3;
            u32 swA = (u32)(((ks * 2 + uu) ^ sA7) << 4);
            u32 swW = (u32)(((ks * 2 + uu) ^ sW7) << 4);
            u32 ahf[2][4], alf[2][4], whf[4][2], wlf[4][2];
            #pragma unroll
            for (int mi = 0; mi < 2; mi++) {
                ldsm4(ahf[mi][0], ahf[mi][1], ahf[mi][2], ahf[mi][3],
                      aRow + stb + (u32)mi * 2048 + swA);
                ldsm4(alf[mi][0], alf[mi][1], alf[mi][2], alf[mi][3],
                      aRow + stb + 16384 + (u32)mi * 2048 + swA);
            }
            #pragma unroll
            for (int nj = 0; nj < 2; nj++) {
                u32 r0, r1, r2, r3;
                ldsm4(r0, r1, r2, r3, wRow + stb + (u32)nj * 2048 + swW);
                whf[2 * nj][0] = r0; whf[2 * nj + 1][0] = r1;
                whf[2 * nj][1] = r2; whf[2 * nj + 1][1] = r3;
                ldsm4(r0, r1, r2, r3, wRow + stb + 8192 + (u32)nj * 2048 + swW);
                wlf[2 * nj][0] = r0; wlf[2 * nj + 1][0] = r1;
                wlf[2 * nj][1] = r2; wlf[2 * nj + 1][1] = r3;
            }
            #pragma unroll
            for (int mi = 0; mi < 2; mi++)
                #pragma unroll
                for (int n = 0; n < 4; n++) {
                    mma_bf16(acc[mi][n], ahf[mi], whf[n]);
                    mma_bf16(acc[mi][n], ahf[mi], wlf[n]);
                    mma_bf16(acc[mi][n], alf[mi], whf[n]);
                }
        }
        __syncthreads();
    }

    int er = lane >> 2, ec = (lane & 3) * 2;
    #pragma unroll
    for (int mi = 0; mi < 2; mi++) {
        int row0 = bm + wm + mi * 16 + er;
        #pragma unroll
        for (int n = 0; n < 4; n++) {
            int col = bn + wn + n * 8 + ec;
            float2 bv = *(const float2*)&bias[col];
            float2 v0 = make_float2(acc[mi][n][0] + bv.x, acc[mi][n][1] + bv.y);
            float2 v1 = make_float2(acc[mi][n][2] + bv.x, acc[mi][n][3] + bv.y);
            *(float2*)&C[(size_t)row0 * DIM + col]       = v0;
            *(float2*)&C[(size_t)(row0 + 8) * DIM + col] = v1;
        }
    }
}

// Fused Q-GEMM (y<32) + K-GEMM (y>=32) single launch
__global__ __launch_bounds__(256, 2)
void qk_gemm_kernel(const __nv_bfloat16* __restrict__ th, const __nv_bfloat16* __restrict__ tl,
                    const __nv_bfloat16* __restrict__ wqh, const __nv_bfloat16* __restrict__ wql,
                    const float* __restrict__ b_q, float* __restrict__ Qb,
                    const __nv_bfloat16* __restrict__ fh, const __nv_bfloat16* __restrict__ fl,
                    const __nv_bfloat16* __restrict__ wkh, const __nv_bfloat16* __restrict__ wkl,
                    const float* __restrict__ b_k, float* __restrict__ Kb) {
    extern __shared__ char smem[];
    int y = blockIdx.y;
    int bn = blockIdx.x * 64;
    if (y < 32) {
        gemm_body(th, tl, wqh, wql, b_q, Qb, y * 128, bn, smem);
    } else {
        gemm_body(fh, fl, wkh, wkl, b_k, Kb, (y - 32) * 128, bn, smem);
    }
}

// O-GEMM single
__global__ __launch_bounds__(256, 2)
void o_gemm_kernel(const __nv_bfloat16* __restrict__ Ah, const __nv_bfloat16* __restrict__ Al,
                   const __nv_bfloat16* __restrict__ Wh, const __nv_bfloat16* __restrict__ Wl,
                   const float* __restrict__ bias, float* __restrict__ C) {
    extern __shared__ char smem[];
    gemm_body(Ah, Al, Wh, Wl, bias, C, blockIdx.y * 128, blockIdx.x * 64, smem);
}

// ---------------------------------------------------------------------------
// Tensor-core flash attention — 64-n KV chunks, 96KB smem, 2 CTAs/SM
// (validated rounds 12-13, unchanged)
// ---------------------------------------------------------------------------
#define AT_STAGE 32768
#define AT_SMEM (32768 + 2 * AT_STAGE)
__global__ __launch_bounds__(256, 2)
void attn_mma_kernel(const __nv_bfloat16* __restrict__ Qh, const __nv_bfloat16* __restrict__ Ql,
                     const __nv_bfloat16* __restrict__ Kh, const __nv_bfloat16* __restrict__ Kl,
                     const __nv_bfloat16* __restrict__ Vth, const __nv_bfloat16* __restrict__ Vtl,
                     __nv_bfloat16* __restrict__ OH, __nv_bfloat16* __restrict__ OL) {
    extern __shared__ char smem[];
    const u32 sb = smem_u32(smem);
    int tid = threadIdx.x;
    int wid = tid >> 5, lane = tid & 31;
    int bh = blockIdx.x;
    int b = bh >> 4, h = bh & 15;
    int t0 = blockIdx.y * 128;

    int lrow = tid >> 1, lhalf = tid & 1;
    int krow = tid >> 2, kq = tid & 3;
    const char* gqh = (const char*)(Qh + ((size_t)(b * TLEN + t0 + lrow)) * DIM + h * HDIM) + lhalf * 64;
    const char* gql = (const char*)(Ql + ((size_t)(b * TLEN + t0 + lrow)) * DIM + h * HDIM) + lhalf * 64;
    const char* gkh = (const char*)(Kh + ((size_t)(b * NLEN + krow)) * DIM + h * HDIM) + kq * 32;
    const char* gkl = (const char*)(Kl + ((size_t)(b * NLEN + krow)) * DIM + h * HDIM) + kq * 32;
    const char* gvh = (const char*)(Vth + ((size_t)(bh * HDIM + krow)) * NLEN) + kq * 32;
    const char* gvl = (const char*)(Vtl + ((size_t)(bh * HDIM + krow)) * NLEN) + kq * 32;

    auto issue_kv = [&](int stage, int c) {
        u32 st = sb + 32768 + (u32)stage * AT_STAGE;
        const char* pkh = gkh + (size_t)c * 131072;
        const char* pkl = gkl + (size_t)c * 131072;
        const char* pvh = gvh + (size_t)c * 128;
        const char* pvl = gvl + (size_t)c * 128;
        u32 kb = st + (u32)krow * 128;
        u32 vb = st + 16384 + (u32)krow * 128;
        #pragma unroll
        for (int j = 0; j < 2; j++) {
            u32 u = (u32)(kq * 2 + j);
            u32 sw = (u ^ (u32)(krow & 7)) << 4;
            cpa(kb + sw, pkh + j * 16);
            cpa(kb + 8192 + sw, pkl + j * 16);
            cpa(vb + sw, pvh + j * 16);
            cpa(vb + 8192 + sw, pvl + j * 16);
        }
        asm volatile("cp.async.commit_group;" ::: "memory");
    };

    {
        u32 qb = sb + (u32)lrow * 128;
        #pragma unroll
        for (int j = 0; j < 4; j++) {
            u32 u = (u32)(lhalf * 4 + j);
            u32 sw = (u ^ (u32)(lrow & 7)) << 4;
            cpa(qb + sw, gqh + j * 16);
            cpa(qb + 16384 + sw, gql + j * 16);
        }
    }
    issue_kv(0, 0);

    float so[8][4];
    #pragma unroll
    for (int f = 0; f < 8; f++)
        #pragma unroll
        for (int q = 0; q < 4; q++) so[f][q] = 0.f;
    float m0 = -INFINITY, m1 = -INFINITY, l0 = 0.f, l1 = 0.f;

    u32 qfh[4][4], qfl[4][4];
    u32 aRow = sb + (u32)(wid * 16 + (lane & 15)) * 128;
    int uu  = lane >> 4;
    int sw7 = lane & 7;

    for (int c = 0; c < 16; c++) {
        if (c + 1 < 16) {
            issue_kv((c + 1) & 1, c + 1);
            asm volatile("cp.async.wait_group 1;" ::: "memory");
        } else {
            asm volatile("cp.async.wait_group 0;" ::: "memory");
        }
        __syncthreads();

        if (c == 0) {
            #pragma unroll
            for (int ks = 0; ks < 4; ks++) {
                u32 sw = (u32)(((ks * 2 + uu) ^ sw7) << 4);
                ldsm4(qfh[ks][0], qfh[ks][1], qfh[ks][2], qfh[ks][3], aRow + sw);
                ldsm4(qfl[ks][0], qfl[ks][1], qfl[ks][2], qfl[ks][3], aRow + 16384 + sw);
            }
        }

        u32 st = sb + 32768 + (u32)(c & 1) * AT_STAGE;
        u32 kBase = st + (u32)(lane & 15) * 128;
        u32 vBase = st + 16384 + (u32)(lane & 15) * 128;

        float s[8][4];
        #pragma unroll
        for (int f = 0; f < 8; f++)
            #pragma unroll
            for (int q = 0; q < 4; q++) s[f][q] = 0.f;
        #pragma unroll
        for (int ks = 0; ks < 4; ks++) {
            u32 sw = (u32)(((ks * 2 + uu) ^ sw7) << 4);
            #pragma unroll
            for (int nj = 0; nj < 4; nj++) {
                u32 ka = kBase + (u32)nj * 2048 + sw;
                u32 h0, h1, h2, h3, e0, e1, e2, e3;
                ldsm4(h0, h1, h2, h3, ka);
                ldsm4(e0, e1, e2, e3, ka + 8192);
                u32 bh0[2] = {h0, h2}, bh1[2] = {h1, h3};
                u32 bl0[2] = {e0, e2}, bl1[2] = {e1, e3};
                mma_bf16(s[2 * nj],     qfh[ks], bh0);
                mma_bf16(s[2 * nj],     qfh[ks], bl0);
                mma_bf16(s[2 * nj],     qfl[ks], bh0);
                mma_bf16(s[2 * nj + 1], qfh[ks], bh1);
                mma_bf16(s[2 * nj + 1], qfh[ks], bl1);
                mma_bf16(s[2 * nj + 1], qfl[ks], bh1);
            }
        }

        float mx0 = -INFINITY, mx1 = -INFINITY;
        #pragma unroll
        for (int f = 0; f < 8; f++) {
            mx0 = fmaxf(mx0, fmaxf(s[f][0], s[f][1]));
            mx1 = fmaxf(mx1, fmaxf(s[f][2], s[f][3]));
        }
        mx0 = fmaxf(mx0, __shfl_xor_sync(0xffffffffu, mx0, 1));
        mx0 = fmaxf(mx0, __shfl_xor_sync(0xffffffffu, mx0, 2));
        mx1 = fmaxf(mx1, __shfl_xor_sync(0xffffffffu, mx1, 1));
        mx1 = fmaxf(mx1, __shfl_xor_sync(0xffffffffu, mx1, 2));
        float mn0 = fmaxf(m0, mx0), mn1 = fmaxf(m1, mx1);
        float sc0 = __expf(m0 - mn0), sc1 = __expf(m1 - mn1);
        m0 = mn0; m1 = mn1;
        float rs0 = 0.f, rs1 = 0.f;
        #pragma unroll
        for (int f = 0; f < 8; f++) {
            s[f][0] = __expf(s[f][0] - mn0); rs0 += s[f][0];
            s[f][1] = __expf(s[f][1] - mn0); rs0 += s[f][1];
            s[f][2] = __expf(s[f][2] - mn1); rs1 += s[f][2];
            s[f][3] = __expf(s[f][3] - mn1); rs1 += s[f][3];
        }
        rs0 += __shfl_xor_sync(0xffffffffu, rs0, 1);
        rs0 += __shfl_xor_sync(0xffffffffu, rs0, 2);
        rs1 += __shfl_xor_sync(0xffffffffu, rs1, 1);
        rs1 += __shfl_xor_sync(0xffffffffu, rs1, 2);
        l0 = l0 * sc0 + rs0;
        l1 = l1 * sc1 + rs1;
        #pragma unroll
        for (int f = 0; f < 8; f++) {
            so[f][0] *= sc0; so[f][1] *= sc0;
            so[f][2] *= sc1; so[f][3] *= sc1;
        }

        #pragma unroll
        for (int j = 0; j < 4; j++) {
            u32 phi[4], plo[4];
            phi[0] = pack_bf16(s[2 * j][0], s[2 * j][1]);
            phi[1] = pack_bf16(s[2 * j][2], s[2 * j][3]);
            phi[2] = pack_bf16(s[2 * j + 1][0], s[2 * j + 1][1]);
            phi[3] = pack_bf16(s[2 * j + 1][2], s[2 * j + 1][3]);
            plo[0] = pack_resid(phi[0], s[2 * j][0], s[2 * j][1]);
            plo[1] = pack_resid(phi[1], s[2 * j][2], s[2 * j][3]);
            plo[2] = pack_resid(phi[2], s[2 * j + 1][0], s[2 * j + 1][1]);
            plo[3] = pack_resid(phi[3], s[2 * j + 1][2], s[2 * j + 1][3]);
            u32 swv = (u32)(((j * 2 + uu) ^ sw7) << 4);
            #pragma unroll
            for (int dj = 0; dj < 4; dj++) {
                u32 va = vBase + (u32)dj * 2048 + swv;
                u32 h0, h1, h2, h3, e0, e1, e2, e3;
                ldsm4(h0, h1, h2, h3, va);
                ldsm4(e0, e1, e2, e3, va + 8192);
                u32 bh0[2] = {h0, h2}, bh1[2] = {h1, h3};
                u32 bl0[2] = {e0, e2}, bl1[2] = {e1, e3};
                mma_bf16(so[2 * dj],     phi, bh0);
                mma_bf16(so[2 * dj],     phi, bl0);
                mma_bf16(so[2 * dj],     plo, bh0);
                mma_bf16(so[2 * dj + 1], phi, bh1);
                mma_bf16(so[2 * dj + 1], phi, bl1);
                mma_bf16(so[2 * dj + 1], plo, bh1);
            }
        }
        __syncthreads();
    }

    float inv0 = 1.f / l0, inv1 = 1.f / l1;
    int r0g = b * TLEN + t0 + wid * 16 + (lane >> 2);
    int colb = h * HDIM + 2 * (lane & 3);
    #pragma unroll
    for (int f = 0; f < 8; f++) {
        float f0 = so[f][0] * inv0, f1 = so[f][1] * inv0;
        float f2 = so[f][2] * inv1, f3 = so[f][3] * inv1;
        int col = colb + f * 8;
        size_t i0 = (size_t)r0g * DIM + col;
        size_t i1 = (size_t)(r0g + 8) * DIM + col;
        u32 hp0 = pack_bf16(f0, f1);
        u32 hp1 = pack_bf16(f2, f3);
        *(u32*)(OH + i0) = hp0;
        *(u32*)(OH + i1) = hp1;
        *(u32*)(OL + i0) = pack_resid(hp0, f0, f1);
        *(u32*)(OL + i1) = pack_resid(hp1, f2, f3);
    }
}

// ---------------------------------------------------------------------------
extern "C" void kernel_launch(void* const* d_in, const int* in_sizes, int n_in,
                              void* d_out, int out_size) {
    const float* text     = (const float*)d_in[0];
    const float* features = (const float*)d_in[1];
    const float* W_q      = (const float*)d_in[2];
    const float* b_q      = (const float*)d_in[3];
    const float* W_k      = (const float*)d_in[4];
    const float* b_k      = (const float*)d_in[5];
    const float* W_o      = (const float*)d_in[6];
    const float* b_o      = (const float*)d_in[7];
    const float* g_feat   = (const float*)d_in[8];
    const float* g_q      = (const float*)d_in[9];
    const float* g_k      = (const float*)d_in[10];
    float* out = (float*)d_out;

    float *Qb, *Kb;
    cudaGetSymbolAddress((void**)&Qb, g_Qbuf);
    cudaGetSymbolAddress((void**)&Kb, g_Kbuf);

    __nv_bfloat16 *th, *tl, *fh, *fl, *ah, *al, *qh, *ql, *kh, *kl, *vth, *vtl;
    __nv_bfloat16 *wqh, *wql, *wkh, *wkl, *woh, *wol;
    cudaGetSymbolAddress((void**)&th,  g_th);
    cudaGetSymbolAddress((void**)&tl,  g_tl);
    cudaGetSymbolAddress((void**)&fh,  g_fh);
    cudaGetSymbolAddress((void**)&fl,  g_fl);
    cudaGetSymbolAddress((void**)&ah,  g_ah);
    cudaGetSymbolAddress((void**)&al,  g_al);
    cudaGetSymbolAddress((void**)&qh,  g_qh);
    cudaGetSymbolAddress((void**)&ql,  g_ql);
    cudaGetSymbolAddress((void**)&kh,  g_kh);
    cudaGetSymbolAddress((void**)&kl,  g_kl);
    cudaGetSymbolAddress((void**)&vth, g_vth);
    cudaGetSymbolAddress((void**)&vtl, g_vtl);
    cudaGetSymbolAddress((void**)&wqh, g_wqh);
    cudaGetSymbolAddress((void**)&wql, g_wql);
    cudaGetSymbolAddress((void**)&wkh, g_wkh);
    cudaGetSymbolAddress((void**)&wkl, g_wkl);
    cudaGetSymbolAddress((void**)&woh, g_woh);
    cudaGetSymbolAddress((void**)&wol, g_wol);

    static int attrs_set = 0;
    static cudaStream_t s2 = 0;
    static cudaEvent_t ev1 = 0, ev2 = 0;
    if (!attrs_set) {
        cudaFuncSetAttribute(qk_gemm_kernel,
                             cudaFuncAttributeMaxDynamicSharedMemorySize, MM_SMEM);
        cudaFuncSetAttribute(o_gemm_kernel,
                             cudaFuncAttributeMaxDynamicSharedMemorySize, MM_SMEM);
        cudaFuncSetAttribute(attn_mma_kernel,
                             cudaFuncAttributeMaxDynamicSharedMemorySize, AT_SMEM);
        if (cudaStreamCreateWithFlags(&s2, cudaStreamNonBlocking) != cudaSuccess) s2 = 0;
        if (s2) {
            if (cudaEventCreateWithFlags(&ev1, cudaEventDisableTiming) != cudaSuccess) { ev1 = 0; }
            if (cudaEventCreateWithFlags(&ev2, cudaEventDisableTiming) != cudaSuccess) { ev2 = 0; }
            if (!ev1 || !ev2) s2 = 0;
        }
        attrs_set = 1;
    }

    const int MT = BATCH * TLEN;   // 4096
    const int MN = BATCH * NLEN;   // 8192

    // 1. weight splits
    convert_split3_kernel<<<dim3((DIM * DIM / 4) / 256, 3), 256>>>(
        W_q, W_k, W_o, wqh, wql, wkh, wkl, woh, wol);

    // 2. text split
    convert_split_kernel<<<(MT * DIM / 4) / 256, 256>>>(text, th, tl);

    // 3. feats = rmsnorm(features) -> bf16 splits
    rmsnorm_split_kernel<<<MN, 256>>>(features, g_feat, 1.0f, fh, fl);

    // 4. V^T transpose on side stream, overlapping qk_gemm
    if (s2) {
        cudaEventRecord(ev1, 0);
        cudaStreamWaitEvent(s2, ev1, 0);
        transpose_vt_kernel<<<dim3(NLEN / 32, HDIM / 32, BATCH * HEADS), dim3(32, 8), 0, s2>>>(
            fh, fl, vth, vtl);
        cudaEventRecord(ev2, s2);
    } else {
        transpose_vt_kernel<<<dim3(NLEN / 32, HDIM / 32, BATCH * HEADS), dim3(32, 8)>>>(
            fh, fl, vth, vtl);
    }

    // 5. fused Q-GEMM + K-GEMM (main stream), CTA 128x64 -> grid (16, 96)
    qk_gemm_kernel<<<dim3(16, 96), 256, MM_SMEM>>>(
        th, tl, wqh, wql, b_q, Qb, fh, fl, wkh, wkl, b_k, Kb);

    // 6. fused rmsnorm Q + K -> bf16 splits
    rmsnorm_split2_kernel<<<MT + MN, 256>>>(Qb, g_q, qh, ql, Kb, g_k, kh, kl, MT);

    // 7. join side stream, then attention
    if (s2) cudaStreamWaitEvent(0, ev2, 0);
    attn_mma_kernel<<<dim3(BATCH * HEADS, TLEN / 128), 256, AT_SMEM>>>(
        qh, ql, kh, kl, vth, vtl, ah, al);

    // 8. out = attnOut @ Wo^T + bo
    o_gemm_kernel<<<dim3(16, MT / 128), 256, MM_SMEM>>>(ah, al, woh, wol, b_o, out);
}

// round 16
// speedup vs baseline: 1.0603x; 1.0603x over previous
#include <cuda_runtime.h>
#include <cuda_bf16.h>
#include <math.h>

#define BATCH 8
#define TLEN 512
#define NLEN 1024
#define DIM 1024
#define HEADS 16
#define HDIM 64

typedef unsigned long long u64;
typedef unsigned int u32;

// ---------------- mma.sync helpers ----------------
__device__ __forceinline__ u32 smem_u32(const void* p) {
    u32 a;
    asm("{ .reg .u64 t; cvta.to.shared.u64 t, %1; cvt.u32.u64 %0, t; }"
        : "=r"(a) : "l"(p));
    return a;
}
__device__ __forceinline__ void ldsm4(u32& r0, u32& r1, u32& r2, u32& r3, u32 addr) {
    asm volatile("ldmatrix.sync.aligned.m8n8.x4.shared.b16 {%0,%1,%2,%3}, [%4];"
                 : "=r"(r0), "=r"(r1), "=r"(r2), "=r"(r3) : "r"(addr));
}
__device__ __forceinline__ void mma_bf16(float* c, const u32* a, const u32* b) {
    asm volatile(
        "mma.sync.aligned.m16n8k16.row.col.f32.bf16.bf16.f32 "
        "{%0,%1,%2,%3}, {%4,%5,%6,%7}, {%8,%9}, {%0,%1,%2,%3};"
        : "+f"(c[0]), "+f"(c[1]), "+f"(c[2]), "+f"(c[3])
        : "r"(a[0]), "r"(a[1]), "r"(a[2]), "r"(a[3]), "r"(b[0]), "r"(b[1]));
}
__device__ __forceinline__ void cpa(u32 s, const void* g) {
    asm volatile("cp.async.cg.shared.global [%0], [%1], 16;" :: "r"(s), "l"(g));
}
__device__ __forceinline__ u32 pack_bf16(float lo, float hi) {
    u32 r;
    asm("cvt.rn.bf16x2.f32 %0, %1, %2;" : "=r"(r) : "f"(hi), "f"(lo));
    return r;
}
__device__ __forceinline__ u32 pack_resid(u32 hp, float lo, float hi) {
    float rl = lo - __bfloat162float(__ushort_as_bfloat16((unsigned short)(hp & 0xFFFFu)));
    float rh = hi - __bfloat162float(__ushort_as_bfloat16((unsigned short)(hp >> 16)));
    return pack_bf16(rl, rh);
}

// ---------------- scratch (no cudaMalloc) ----------------
__device__ float g_Qbuf[BATCH * TLEN * DIM];
__device__ float g_Kbuf[BATCH * NLEN * DIM];

__device__ __nv_bfloat16 g_th[BATCH * TLEN * DIM];
__device__ __nv_bfloat16 g_tl[BATCH * TLEN * DIM];
__device__ __nv_bfloat16 g_fh[BATCH * NLEN * DIM];
__device__ __nv_bfloat16 g_fl[BATCH * NLEN * DIM];
__device__ __nv_bfloat16 g_ah[BATCH * TLEN * DIM];
__device__ __nv_bfloat16 g_al[BATCH * TLEN * DIM];
__device__ __nv_bfloat16 g_qh[BATCH * TLEN * DIM];
__device__ __nv_bfloat16 g_ql[BATCH * TLEN * DIM];
__device__ __nv_bfloat16 g_kh[BATCH * NLEN * DIM];
__device__ __nv_bfloat16 g_kl[BATCH * NLEN * DIM];
__device__ __nv_bfloat16 g_vth[BATCH * NLEN * DIM];
__device__ __nv_bfloat16 g_vtl[BATCH * NLEN * DIM];
__device__ __nv_bfloat16 g_wqh[DIM * DIM];
__device__ __nv_bfloat16 g_wql[DIM * DIM];
__device__ __nv_bfloat16 g_wkh[DIM * DIM];
__device__ __nv_bfloat16 g_wkl[DIM * DIM];
__device__ __nv_bfloat16 g_woh[DIM * DIM];
__device__ __nv_bfloat16 g_wol[DIM * DIM];

// ---------------------------------------------------------------------------
// Split fp32 -> bf16 hi/lo (single tensor)
// ---------------------------------------------------------------------------
__global__ void convert_split_kernel(const float* __restrict__ in,
                                     __nv_bfloat16* __restrict__ hi,
                                     __nv_bfloat16* __restrict__ lo) {
    int i = blockIdx.x * blockDim.x + threadIdx.x;
    float4 v = ((const float4*)in)[i];
    __nv_bfloat16 h0 = __float2bfloat16(v.x);
    __nv_bfloat16 h1 = __float2bfloat16(v.y);
    __nv_bfloat16 h2 = __float2bfloat16(v.z);
    __nv_bfloat16 h3 = __float2bfloat16(v.w);
    __nv_bfloat16 l0 = __float2bfloat16(v.x - __bfloat162float(h0));
    __nv_bfloat16 l1 = __float2bfloat16(v.y - __bfloat162float(h1));
    __nv_bfloat16 l2 = __float2bfloat16(v.z - __bfloat162float(h2));
    __nv_bfloat16 l3 = __float2bfloat16(v.w - __bfloat162float(h3));
    __nv_bfloat162* H = (__nv_bfloat162*)hi;
    __nv_bfloat162* L = (__nv_bfloat162*)lo;
    H[2 * i]     = __nv_bfloat162(h0, h1);
    H[2 * i + 1] = __nv_bfloat162(h2, h3);
    L[2 * i]     = __nv_bfloat162(l0, l1);
    L[2 * i + 1] = __nv_bfloat162(l2, l3);
}

// batched weight split
__global__ void convert_split3_kernel(const float* __restrict__ w0,
                                      const float* __restrict__ w1,
                                      const float* __restrict__ w2,
                                      __nv_bfloat16* __restrict__ h0p,
                                      __nv_bfloat16* __restrict__ l0p,
                                      __nv_bfloat16* __restrict__ h1p,
                                      __nv_bfloat16* __restrict__ l1p,
                                      __nv_bfloat16* __restrict__ h2p,
                                      __nv_bfloat16* __restrict__ l2p) {
    int z = blockIdx.y;
    const float* in = z == 0 ? w0 : (z == 1 ? w1 : w2);
    __nv_bfloat16* hi = z == 0 ? h0p : (z == 1 ? h1p : h2p);
    __nv_bfloat16* lo = z == 0 ? l0p : (z == 1 ? l1p : l2p);
    int i = blockIdx.x * blockDim.x + threadIdx.x;
    float4 v = ((const float4*)in)[i];
    __nv_bfloat16 a0 = __float2bfloat16(v.x);
    __nv_bfloat16 a1 = __float2bfloat16(v.y);
    __nv_bfloat16 a2 = __float2bfloat16(v.z);
    __nv_bfloat16 a3 = __float2bfloat16(v.w);
    __nv_bfloat16 b0 = __float2bfloat16(v.x - __bfloat162float(a0));
    __nv_bfloat16 b1 = __float2bfloat16(v.y - __bfloat162float(a1));
    __nv_bfloat16 b2 = __float2bfloat16(v.z - __bfloat162float(a2));
    __nv_bfloat16 b3 = __float2bfloat16(v.w - __bfloat162float(a3));
    __nv_bfloat162* H = (__nv_bfloat162*)hi;
    __nv_bfloat162* L = (__nv_bfloat162*)lo;
    H[2 * i]     = __nv_bfloat162(a0, a1);
    H[2 * i + 1] = __nv_bfloat162(a2, a3);
    L[2 * i]     = __nv_bfloat162(b0, b1);
    L[2 * i + 1] = __nv_bfloat162(b2, b3);
}

// ---------------------------------------------------------------------------
// RMSNorm -> scaled bf16 hi/lo split (single input)
// ---------------------------------------------------------------------------
__global__ void rmsnorm_split_kernel(const float* __restrict__ in,
                                     const float* __restrict__ g,
                                     float scale,
                                     __nv_bfloat16* __restrict__ hi,
                                     __nv_bfloat16* __restrict__ lo) {
    int row = blockIdx.x;
    int tid = threadIdx.x;
    const float4* x4 = (const float4*)(in + (size_t)row * DIM);
    float4 v = x4[tid];
    float s = v.x * v.x + v.y * v.y + v.z * v.z + v.w * v.w;
    #pragma unroll
    for (int o = 16; o > 0; o >>= 1) s += __shfl_xor_sync(0xffffffffu, s, o);
    __shared__ float ws[8];
    __shared__ float rsh;
    if ((tid & 31) == 0) ws[tid >> 5] = s;
    __syncthreads();
    if (tid == 0) {
        float t = 0.f;
        #pragma unroll
        for (int i = 0; i < 8; i++) t += ws[i];
        rsh = rsqrtf(t * (1.0f / DIM) + 1e-6f);
    }
    __syncthreads();
    float r = rsh * scale;
    float4 gv = ((const float4*)g)[tid];
    float ox = v.x * r * gv.x, oy = v.y * r * gv.y;
    float oz = v.z * r * gv.z, ow = v.w * r * gv.w;
    __nv_bfloat16 h0 = __float2bfloat16(ox);
    __nv_bfloat16 h1 = __float2bfloat16(oy);
    __nv_bfloat16 h2 = __float2bfloat16(oz);
    __nv_bfloat16 h3 = __float2bfloat16(ow);
    __nv_bfloat16 e0 = __float2bfloat16(ox - __bfloat162float(h0));
    __nv_bfloat16 e1 = __float2bfloat16(oy - __bfloat162float(h1));
    __nv_bfloat16 e2 = __float2bfloat16(oz - __bfloat162float(h2));
    __nv_bfloat16 e3 = __float2bfloat16(ow - __bfloat162float(h3));
    size_t base = (size_t)row * DIM + tid * 4;
    __nv_bfloat162* H = (__nv_bfloat162*)(hi + base);
    __nv_bfloat162* L = (__nv_bfloat162*)(lo + base);
    H[0] = __nv_bfloat162(h0, h1); H[1] = __nv_bfloat162(h2, h3);
    L[0] = __nv_bfloat162(e0, e1); L[1] = __nv_bfloat162(e2, e3);
}

// Fused rmsnorm for Q (rows 0..mt-1) and K (rows mt..)
__global__ void rmsnorm_split2_kernel(const float* __restrict__ inQ,
                                      const float* __restrict__ gq,
                                      __nv_bfloat16* __restrict__ qh,
                                      __nv_bfloat16* __restrict__ ql,
                                      const float* __restrict__ inK,
                                      const float* __restrict__ gk,
                                      __nv_bfloat16* __restrict__ kh,
                                      __nv_bfloat16* __restrict__ kl,
                                      int mt) {
    int row = blockIdx.x;
    const float* in; const float* g; float scale;
    __nv_bfloat16 *hi, *lo;
    if (row < mt) {
        in = inQ; g = gq; scale = 0.125f; hi = qh; lo = ql;
    } else {
        in = inK; g = gk; scale = 1.0f; hi = kh; lo = kl; row -= mt;
    }
    int tid = threadIdx.x;
    const float4* x4 = (const float4*)(in + (size_t)row * DIM);
    float4 v = x4[tid];
    float s = v.x * v.x + v.y * v.y + v.z * v.z + v.w * v.w;
    #pragma unroll
    for (int o = 16; o > 0; o >>= 1) s += __shfl_xor_sync(0xffffffffu, s, o);
    __shared__ float ws[8];
    __shared__ float rsh;
    if ((tid & 31) == 0) ws[tid >> 5] = s;
    __syncthreads();
    if (tid == 0) {
        float t = 0.f;
        #pragma unroll
        for (int i = 0; i < 8; i++) t += ws[i];
        rsh = rsqrtf(t * (1.0f / DIM) + 1e-6f);
    }
    __syncthreads();
    float r = rsh * scale;
    float4 gv = ((const float4*)g)[tid];
    float ox = v.x * r * gv.x, oy = v.y * r * gv.y;
    float oz = v.z * r * gv.z, ow = v.w * r * gv.w;
    __nv_bfloat16 h0 = __float2bfloat16(ox);
    __nv_bfloat16 h1 = __float2bfloat16(oy);
    __nv_bfloat16 h2 = __float2bfloat16(oz);
    __nv_bfloat16 h3 = __float2bfloat16(ow);
    __nv_bfloat16 e0 = __float2bfloat16(ox - __bfloat162float(h0));
    __nv_bfloat16 e1 = __float2bfloat16(oy - __bfloat162float(h1));
    __nv_bfloat16 e2 = __float2bfloat16(oz - __bfloat162float(h2));
    __nv_bfloat16 e3 = __float2bfloat16(ow - __bfloat162float(h3));
    size_t base = (size_t)row * DIM + tid * 4;
    __nv_bfloat162* H = (__nv_bfloat162*)(hi + base);
    __nv_bfloat162* L = (__nv_bfloat162*)(lo + base);
    H[0] = __nv_bfloat162(h0, h1); H[1] = __nv_bfloat162(h2, h3);
    L[0] = __nv_bfloat162(e0, e1); L[1] = __nv_bfloat162(e2, e3);
}

// ---------------------------------------------------------------------------
// Transpose feats splits into V^T per (b,h)
// ---------------------------------------------------------------------------
__global__ void transpose_vt_kernel(const __nv_bfloat16* __restrict__ fh,
                                    const __nv_bfloat16* __restrict__ fl,
                                    __nv_bfloat16* __restrict__ vth,
                                    __nv_bfloat16* __restrict__ vtl) {
    __shared__ __nv_bfloat16 tH[32][34];
    __shared__ __nv_bfloat16 tL[32][34];
    int bh = blockIdx.z;
    int b = bh >> 4, h = bh & 15;
    int n0 = blockIdx.x * 32, d0 = blockIdx.y * 32;
    int tx = threadIdx.x, ty = threadIdx.y;
    #pragma unroll
    for (int i = 0; i < 4; i++) {
        int n = n0 + ty + i * 8;
        size_t src = (size_t)(b * NLEN + n) * DIM + h * HDIM + d0 + tx;
        tH[ty + i * 8][tx] = fh[src];
        tL[ty + i * 8][tx] = fl[src];
    }
    __syncthreads();
    #pragma unroll
    for (int i = 0; i < 4; i++) {
        int d = d0 + ty + i * 8;
        size_t dst = ((size_t)bh * HDIM + d) * NLEN + n0 + tx;
        vth[dst] = tH[tx][ty + i * 8];
        vtl[dst] = tL[tx][ty + i * 8];
    }
}

// ---------------------------------------------------------------------------
// Tensor-core GEMM body — 512 threads (16 warps, 4x4), warp tile 32x32.
// CTA 128x128, K-chunks 64, 2-stage cp.async. Per-warp ks stagger.
// (validated round 13, byte-identical)
// ---------------------------------------------------------------------------
#define MM_SMEM (2 * 4 * 16384)
__device__ __forceinline__
void gemm_body(const __nv_bfloat16* Ah, const __nv_bfloat16* Al,
               const __nv_bfloat16* Wh, const __nv_bfloat16* Wl,
               const float* bias, float* C, int bm, int bn, char* smem) {
    const u32 sb = smem_u32(smem);
    int tid  = threadIdx.x;
    int wid  = tid >> 5, lane = tid & 31;
    int wm = (wid >> 2) * 32;
    int wn = (wid & 3) * 32;
    int ko = wid & 3;

    int lrow = tid >> 2;
    int lq   = tid & 3;
    const char* gAh = (const char*)(Ah + (size_t)(bm + lrow) * DIM) + lq * 32;
    const char* gAl = (const char*)(Al + (size_t)(bm + lrow) * DIM) + lq * 32;
    const char* gWh = (const char*)(Wh + (size_t)(bn + lrow) * DIM) + lq * 32;
    const char* gWl = (const char*)(Wl + (size_t)(bn + lrow) * DIM) + lq * 32;

    float acc[2][4][4];
    #pragma unroll
    for (int mi = 0; mi < 2; mi++)
        #pragma unroll
        for (int n = 0; n < 4; n++)
            #pragma unroll
            for (int q = 0; q < 4; q++) acc[mi][n][q] = 0.f;

    int rA = wm + (lane & 15);
    int rW = wn + (lane & 15);
    u32 aRow = sb + (u32)rA * 128;
    u32 wRow = sb + (u32)rW * 128;
    int uu  = lane >> 4;
    int sA7 = rA & 7, sW7 = rW & 7;

    auto issue_stage = [&](int stage, int c) {
        u32 base = sb + (u32)stage * 65536 + (u32)lrow * 128;
        const char* pa = gAh + c * 128;
        const char* pb = gAl + c * 128;
        const char* pc = gWh + c * 128;
        const char* pd = gWl + c * 128;
        #pragma unroll
        for (int j = 0; j < 2; j++) {
            int u = lq * 2 + j;
            u32 sw = (u32)((u ^ (lrow & 7)) << 4);
            cpa(base +         sw, pa + j * 16);
            cpa(base + 16384 + sw, pb + j * 16);
            cpa(base + 32768 + sw, pc + j * 16);
            cpa(base + 49152 + sw, pd + j * 16);
        }
        asm volatile("cp.async.commit_group;" ::: "memory");
    };

    issue_stage(0, 0);

    for (int c = 0; c < 16; c++) {
        int buf = c & 1;
        if (c + 1 < 16) {
            issue_stage(buf ^ 1, c + 1);
            asm volatile("cp.async.wait_group 1;" ::: "memory");
        } else {
            asm volatile("cp.async.wait_group 0;" ::: "memory");
        }
        __syncthreads();

        u32 stb = (u32)buf * 65536;
        #pragma unroll
        for (int ki = 0; ki < 4; ki++) {
            int ks = (ki + ko) & 3;
            u32 swA = (u32)(((ks * 2 + uu) ^ sA7) << 4);
            u32 swW = (u32)(((ks * 2 + uu) ^ sW7) << 4);
            u32 ahf[2][4], alf[2][4], whf[4][2], wlf[4][2];
            #pragma unroll
            for (int mi = 0; mi < 2; mi++) {
                ldsm4(ahf[mi][0], ahf[mi][1], ahf[mi][2], ahf[mi][3],
                      aRow + stb + (u32)mi * 2048 + swA);
                ldsm4(alf[mi][0], alf[mi][1], alf[mi][2], alf[mi][3],
                      aRow + stb + 16384 + (u32)mi * 2048 + swA);
            }
            #pragma unroll
            for (int nj = 0; nj < 2; nj++) {
                u32 r0, r1, r2, r3;
                ldsm4(r0, r1, r2, r3, wRow + stb + 32768 + (u32)nj * 2048 + swW);
                whf[2 * nj][0] = r0; whf[2 * nj + 1][0] = r1;
                whf[2 * nj][1] = r2; whf[2 * nj + 1][1] = r3;
                ldsm4(r0, r1, r2, r3, wRow + stb + 49152 + (u32)nj * 2048 + swW);
                wlf[2 * nj][0] = r0; wlf[2 * nj + 1][0] = r1;
                wlf[2 * nj][1] = r2; wlf[2 * nj + 1][1] = r3;
            }
            #pragma unroll
            for (int mi = 0; mi < 2; mi++)
                #pragma unroll
                for (int n = 0; n < 4; n++) {
                    mma_bf16(acc[mi][n], ahf[mi], whf[n]);
                    mma_bf16(acc[mi][n], ahf[mi], wlf[n]);
                    mma_bf16(acc[mi][n], alf[mi], whf[n]);
                }
        }
        __syncthreads();
    }

    int er = lane >> 2, ec = (lane & 3) * 2;
    #pragma unroll
    for (int mi = 0; mi < 2; mi++) {
        int row0 = bm + wm + mi * 16 + er;
        #pragma unroll
        for (int n = 0; n < 4; n++) {
            int col = bn + wn + n * 8 + ec;
            float2 bv = *(const float2*)&bias[col];
            float2 v0 = make_float2(acc[mi][n][0] + bv.x, acc[mi][n][1] + bv.y);
            float2 v1 = make_float2(acc[mi][n][2] + bv.x, acc[mi][n][3] + bv.y);
            *(float2*)&C[(size_t)row0 * DIM + col]       = v0;
            *(float2*)&C[(size_t)(row0 + 8) * DIM + col] = v1;
        }
    }
}

// Fused Q-GEMM (y<32) + K-GEMM (y>=32) single launch
__global__ __launch_bounds__(512)
void qk_gemm_kernel(const __nv_bfloat16* __restrict__ th, const __nv_bfloat16* __restrict__ tl,
                    const __nv_bfloat16* __restrict__ wqh, const __nv_bfloat16* __restrict__ wql,
                    const float* __restrict__ b_q, float* __restrict__ Qb,
                    const __nv_bfloat16* __restrict__ fh, const __nv_bfloat16* __restrict__ fl,
                    const __nv_bfloat16* __restrict__ wkh, const __nv_bfloat16* __restrict__ wkl,
                    const float* __restrict__ b_k, float* __restrict__ Kb) {
    extern __shared__ char smem[];
    int y = blockIdx.y;
    int bn = blockIdx.x * 128;
    if (y < 32) {
        gemm_body(th, tl, wqh, wql, b_q, Qb, y * 128, bn, smem);
    } else {
        gemm_body(fh, fl, wkh, wkl, b_k, Kb, (y - 32) * 128, bn, smem);
    }
}

// O-GEMM single
__global__ __launch_bounds__(512)
void o_gemm_kernel(const __nv_bfloat16* __restrict__ Ah, const __nv_bfloat16* __restrict__ Al,
                   const __nv_bfloat16* __restrict__ Wh, const __nv_bfloat16* __restrict__ Wl,
                   const float* __restrict__ bias, float* __restrict__ C) {
    extern __shared__ char smem[];
    gemm_body(Ah, Al, Wh, Wl, bias, C, blockIdx.y * 128, blockIdx.x * 128, smem);
}

// ---------------------------------------------------------------------------
// Tensor-core flash attention — 64-n KV chunks, 96KB smem, 2 CTAs/SM
// (validated rounds 12-13, unchanged)
// ---------------------------------------------------------------------------
#define AT_STAGE 32768
#define AT_SMEM (32768 + 2 * AT_STAGE)
__global__ __launch_bounds__(256, 2)
void attn_mma_kernel(const __nv_bfloat16* __restrict__ Qh, const __nv_bfloat16* __restrict__ Ql,
                     const __nv_bfloat16* __restrict__ Kh, const __nv_bfloat16* __restrict__ Kl,
                     const __nv_bfloat16* __restrict__ Vth, const __nv_bfloat16* __restrict__ Vtl,
                     __nv_bfloat16* __restrict__ OH, __nv_bfloat16* __restrict__ OL) {
    extern __shared__ char smem[];
    const u32 sb = smem_u32(smem);
    int tid = threadIdx.x;
    int wid = tid >> 5, lane = tid & 31;
    int bh = blockIdx.x;
    int b = bh >> 4, h = bh & 15;
    int t0 = blockIdx.y * 128;

    int lrow = tid >> 1, lhalf = tid & 1;
    int krow = tid >> 2, kq = tid & 3;
    const char* gqh = (const char*)(Qh + ((size_t)(b * TLEN + t0 + lrow)) * DIM + h * HDIM) + lhalf * 64;
    const char* gql = (const char*)(Ql + ((size_t)(b * TLEN + t0 + lrow)) * DIM + h * HDIM) + lhalf * 64;
    const char* gkh = (const char*)(Kh + ((size_t)(b * NLEN + krow)) * DIM + h * HDIM) + kq * 32;
    const char* gkl = (const char*)(Kl + ((size_t)(b * NLEN + krow)) * DIM + h * HDIM) + kq * 32;
    const char* gvh = (const char*)(Vth + ((size_t)(bh * HDIM + krow)) * NLEN) + kq * 32;
    const char* gvl = (const char*)(Vtl + ((size_t)(bh * HDIM + krow)) * NLEN) + kq * 32;

    auto issue_kv = [&](int stage, int c) {
        u32 st = sb + 32768 + (u32)stage * AT_STAGE;
        const char* pkh = gkh + (size_t)c * 131072;
        const char* pkl = gkl + (size_t)c * 131072;
        const char* pvh = gvh + (size_t)c * 128;
        const char* pvl = gvl + (size_t)c * 128;
        u32 kb = st + (u32)krow * 128;
        u32 vb = st + 16384 + (u32)krow * 128;
        #pragma unroll
        for (int j = 0; j < 2; j++) {
            u32 u = (u32)(kq * 2 + j);
            u32 sw = (u ^ (u32)(krow & 7)) << 4;
            cpa(kb + sw, pkh + j * 16);
            cpa(kb + 8192 + sw, pkl + j * 16);
            cpa(vb + sw, pvh + j * 16);
            cpa(vb + 8192 + sw, pvl + j * 16);
        }
        asm volatile("cp.async.commit_group;" ::: "memory");
    };

    {
        u32 qb = sb + (u32)lrow * 128;
        #pragma unroll
        for (int j = 0; j < 4; j++) {
            u32 u = (u32)(lhalf * 4 + j);
            u32 sw = (u ^ (u32)(lrow & 7)) << 4;
            cpa(qb + sw, gqh + j * 16);
            cpa(qb + 16384 + sw, gql + j * 16);
        }
    }
    issue_kv(0, 0);

    float so[8][4];
    #pragma unroll
    for (int f = 0; f < 8; f++)
        #pragma unroll
        for (int q = 0; q < 4; q++) so[f][q] = 0.f;
    float m0 = -INFINITY, m1 = -INFINITY, l0 = 0.f, l1 = 0.f;

    u32 qfh[4][4], qfl[4][4];
    u32 aRow = sb + (u32)(wid * 16 + (lane & 15)) * 128;
    int uu  = lane >> 4;
    int sw7 = lane & 7;

    for (int c = 0; c < 16; c++) {
        if (c + 1 < 16) {
            issue_kv((c + 1) & 1, c + 1);
            asm volatile("cp.async.wait_group 1;" ::: "memory");
        } else {
            asm volatile("cp.async.wait_group 0;" ::: "memory");
        }
        __syncthreads();

        if (c == 0) {
            #pragma unroll
            for (int ks = 0; ks < 4; ks++) {
                u32 sw = (u32)(((ks * 2 + uu) ^ sw7) << 4);
                ldsm4(qfh[ks][0], qfh[ks][1], qfh[ks][2], qfh[ks][3], aRow + sw);
                ldsm4(qfl[ks][0], qfl[ks][1], qfl[ks][2], qfl[ks][3], aRow + 16384 + sw);
            }
        }

        u32 st = sb + 32768 + (u32)(c & 1) * AT_STAGE;
        u32 kBase = st + (u32)(lane & 15) * 128;
        u32 vBase = st + 16384 + (u32)(lane & 15) * 128;

        float s[8][4];
        #pragma unroll
        for (int f = 0; f < 8; f++)
            #pragma unroll
            for (int q = 0; q < 4; q++) s[f][q] = 0.f;
        #pragma unroll
        for (int ks = 0; ks < 4; ks++) {
            u32 sw = (u32)(((ks * 2 + uu) ^ sw7) << 4);
            #pragma unroll
            for (int nj = 0; nj < 4; nj++) {
                u32 ka = kBase + (u32)nj * 2048 + sw;
                u32 h0, h1, h2, h3, e0, e1, e2, e3;
                ldsm4(h0, h1, h2, h3, ka);
                ldsm4(e0, e1, e2, e3, ka + 8192);
                u32 bh0[2] = {h0, h2}, bh1[2] = {h1, h3};
                u32 bl0[2] = {e0, e2}, bl1[2] = {e1, e3};
                mma_bf16(s[2 * nj],     qfh[ks], bh0);
                mma_bf16(s[2 * nj],     qfh[ks], bl0);
                mma_bf16(s[2 * nj],     qfl[ks], bh0);
                mma_bf16(s[2 * nj + 1], qfh[ks], bh1);
                mma_bf16(s[2 * nj + 1], qfh[ks], bl1);
                mma_bf16(s[2 * nj + 1], qfl[ks], bh1);
            }
        }

        float mx0 = -INFINITY, mx1 = -INFINITY;
        #pragma unroll
        for (int f = 0; f < 8; f++) {
            mx0 = fmaxf(mx0, fmaxf(s[f][0], s[f][1]));
            mx1 = fmaxf(mx1, fmaxf(s[f][2], s[f][3]));
        }
        mx0 = fmaxf(mx0, __shfl_xor_sync(0xffffffffu, mx0, 1));
        mx0 = fmaxf(mx0, __shfl_xor_sync(0xffffffffu, mx0, 2));
        mx1 = fmaxf(mx1, __shfl_xor_sync(0xffffffffu, mx1, 1));
        mx1 = fmaxf(mx1, __shfl_xor_sync(0xffffffffu, mx1, 2));
        float mn0 = fmaxf(m0, mx0), mn1 = fmaxf(m1, mx1);
        float sc0 = __expf(m0 - mn0), sc1 = __expf(m1 - mn1);
        m0 = mn0; m1 = mn1;
        float rs0 = 0.f, rs1 = 0.f;
        #pragma unroll
        for (int f = 0; f < 8; f++) {
            s[f][0] = __expf(s[f][0] - mn0); rs0 += s[f][0];
            s[f][1] = __expf(s[f][1] - mn0); rs0 += s[f][1];
            s[f][2] = __expf(s[f][2] - mn1); rs1 += s[f][2];
            s[f][3] = __expf(s[f][3] - mn1); rs1 += s[f][3];
        }
        rs0 += __shfl_xor_sync(0xffffffffu, rs0, 1);
        rs0 += __shfl_xor_sync(0xffffffffu, rs0, 2);
        rs1 += __shfl_xor_sync(0xffffffffu, rs1, 1);
        rs1 += __shfl_xor_sync(0xffffffffu, rs1, 2);
        l0 = l0 * sc0 + rs0;
        l1 = l1 * sc1 + rs1;
        #pragma unroll
        for (int f = 0; f < 8; f++) {
            so[f][0] *= sc0; so[f][1] *= sc0;
            so[f][2] *= sc1; so[f][3] *= sc1;
        }

        #pragma unroll
        for (int j = 0; j < 4; j++) {
            u32 phi[4], plo[4];
            phi[0] = pack_bf16(s[2 * j][0], s[2 * j][1]);
            phi[1] = pack_bf16(s[2 * j][2], s[2 * j][3]);
            phi[2] = pack_bf16(s[2 * j + 1][0], s[2 * j + 1][1]);
            phi[3] = pack_bf16(s[2 * j + 1][2], s[2 * j + 1][3]);
            plo[0] = pack_resid(phi[0], s[2 * j][0], s[2 * j][1]);
            plo[1] = pack_resid(phi[1], s[2 * j][2], s[2 * j][3]);
            plo[2] = pack_resid(phi[2], s[2 * j + 1][0], s[2 * j + 1][1]);
            plo[3] = pack_resid(phi[3], s[2 * j + 1][2], s[2 * j + 1][3]);
            u32 swv = (u32)(((j * 2 + uu) ^ sw7) << 4);
            #pragma unroll
            for (int dj = 0; dj < 4; dj++) {
                u32 va = vBase + (u32)dj * 2048 + swv;
                u32 h0, h1, h2, h3, e0, e1, e2, e3;
                ldsm4(h0, h1, h2, h3, va);
                ldsm4(e0, e1, e2, e3, va + 8192);
                u32 bh0[2] = {h0, h2}, bh1[2] = {h1, h3};
                u32 bl0[2] = {e0, e2}, bl1[2] = {e1, e3};
                mma_bf16(so[2 * dj],     phi, bh0);
                mma_bf16(so[2 * dj],     phi, bl0);
                mma_bf16(so[2 * dj],     plo, bh0);
                mma_bf16(so[2 * dj + 1], phi, bh1);
                mma_bf16(so[2 * dj + 1], phi, bl1);
                mma_bf16(so[2 * dj + 1], plo, bh1);
            }
        }
        __syncthreads();
    }

    float inv0 = 1.f / l0, inv1 = 1.f / l1;
    int r0g = b * TLEN + t0 + wid * 16 + (lane >> 2);
    int colb = h * HDIM + 2 * (lane & 3);
    #pragma unroll
    for (int f = 0; f < 8; f++) {
        float f0 = so[f][0] * inv0, f1 = so[f][1] * inv0;
        float f2 = so[f][2] * inv1, f3 = so[f][3] * inv1;
        int col = colb + f * 8;
        size_t i0 = (size_t)r0g * DIM + col;
        size_t i1 = (size_t)(r0g + 8) * DIM + col;
        u32 hp0 = pack_bf16(f0, f1);
        u32 hp1 = pack_bf16(f2, f3);
        *(u32*)(OH + i0) = hp0;
        *(u32*)(OH + i1) = hp1;
        *(u32*)(OL + i0) = pack_resid(hp0, f0, f1);
        *(u32*)(OL + i1) = pack_resid(hp1, f2, f3);
    }
}

// ---------------------------------------------------------------------------
extern "C" void kernel_launch(void* const* d_in, const int* in_sizes, int n_in,
                              void* d_out, int out_size) {
    const float* text     = (const float*)d_in[0];
    const float* features = (const float*)d_in[1];
    const float* W_q      = (const float*)d_in[2];
    const float* b_q      = (const float*)d_in[3];
    const float* W_k      = (const float*)d_in[4];
    const float* b_k      = (const float*)d_in[5];
    const float* W_o      = (const float*)d_in[6];
    const float* b_o      = (const float*)d_in[7];
    const float* g_feat   = (const float*)d_in[8];
    const float* g_q      = (const float*)d_in[9];
    const float* g_k      = (const float*)d_in[10];
    float* out = (float*)d_out;

    float *Qb, *Kb;
    cudaGetSymbolAddress((void**)&Qb, g_Qbuf);
    cudaGetSymbolAddress((void**)&Kb, g_Kbuf);

    __nv_bfloat16 *th, *tl, *fh, *fl, *ah, *al, *qh, *ql, *kh, *kl, *vth, *vtl;
    __nv_bfloat16 *wqh, *wql, *wkh, *wkl, *woh, *wol;
    cudaGetSymbolAddress((void**)&th,  g_th);
    cudaGetSymbolAddress((void**)&tl,  g_tl);
    cudaGetSymbolAddress((void**)&fh,  g_fh);
    cudaGetSymbolAddress((void**)&fl,  g_fl);
    cudaGetSymbolAddress((void**)&ah,  g_ah);
    cudaGetSymbolAddress((void**)&al,  g_al);
    cudaGetSymbolAddress((void**)&qh,  g_qh);
    cudaGetSymbolAddress((void**)&ql,  g_ql);
    cudaGetSymbolAddress((void**)&kh,  g_kh);
    cudaGetSymbolAddress((void**)&kl,  g_kl);
    cudaGetSymbolAddress((void**)&vth, g_vth);
    cudaGetSymbolAddress((void**)&vtl, g_vtl);
    cudaGetSymbolAddress((void**)&wqh, g_wqh);
    cudaGetSymbolAddress((void**)&wql, g_wql);
    cudaGetSymbolAddress((void**)&wkh, g_wkh);
    cudaGetSymbolAddress((void**)&wkl, g_wkl);
    cudaGetSymbolAddress((void**)&woh, g_woh);
    cudaGetSymbolAddress((void**)&wol, g_wol);

    static int attrs_set = 0;
    static cudaStream_t s2 = 0;
    static cudaEvent_t ev0 = 0, ev1 = 0, ev2 = 0, ev3 = 0;
    if (!attrs_set) {
        cudaFuncSetAttribute(qk_gemm_kernel,
                             cudaFuncAttributeMaxDynamicSharedMemorySize, MM_SMEM);
        cudaFuncSetAttribute(o_gemm_kernel,
                             cudaFuncAttributeMaxDynamicSharedMemorySize, MM_SMEM);
        cudaFuncSetAttribute(attn_mma_kernel,
                             cudaFuncAttributeMaxDynamicSharedMemorySize, AT_SMEM);
        if (cudaStreamCreateWithFlags(&s2, cudaStreamNonBlocking) != cudaSuccess) s2 = 0;
        if (s2) {
            if (cudaEventCreateWithFlags(&ev0, cudaEventDisableTiming) != cudaSuccess) ev0 = 0;
            if (cudaEventCreateWithFlags(&ev1, cudaEventDisableTiming) != cudaSuccess) ev1 = 0;
            if (cudaEventCreateWithFlags(&ev2, cudaEventDisableTiming) != cudaSuccess) ev2 = 0;
            if (cudaEventCreateWithFlags(&ev3, cudaEventDisableTiming) != cudaSuccess) ev3 = 0;
            if (!ev0 || !ev1 || !ev2 || !ev3) s2 = 0;
        }
        attrs_set = 1;
    }

    const int MT = BATCH * TLEN;   // 4096
    const int MN = BATCH * NLEN;   // 8192

    if (s2) {
        // Fork side stream FROM the captured stream before using it
        // (required for legal cross-stream work during graph capture).
        cudaEventRecord(ev0, 0);
        cudaStreamWaitEvent(s2, ev0, 0);

        // side stream: weight splits (consumed by qk_gemm + o_gemm)
        convert_split3_kernel<<<dim3((DIM * DIM / 4) / 256, 3), 256, 0, s2>>>(
            W_q, W_k, W_o, wqh, wql, wkh, wkl, woh, wol);
        cudaEventRecord(ev3, s2);

        // main stream: text split + feats rmsnorm (independent of weights)
        convert_split_kernel<<<(MT * DIM / 4) / 256, 256>>>(text, th, tl);
        rmsnorm_split_kernel<<<MN, 256>>>(features, g_feat, 1.0f, fh, fl);
        cudaEventRecord(ev1, 0);

        // side stream: transpose V^T after feats ready (overlaps qk_gemm)
        cudaStreamWaitEvent(s2, ev1, 0);
        transpose_vt_kernel<<<dim3(NLEN / 32, HDIM / 32, BATCH * HEADS), dim3(32, 8), 0, s2>>>(
            fh, fl, vth, vtl);
        cudaEventRecord(ev2, s2);

        // main stream: qk_gemm waits for weights
        cudaStreamWaitEvent(0, ev3, 0);
        qk_gemm_kernel<<<dim3(8, 96), 512, MM_SMEM>>>(
            th, tl, wqh, wql, b_q, Qb, fh, fl, wkh, wkl, b_k, Kb);

        rmsnorm_split2_kernel<<<MT + MN, 256>>>(Qb, g_q, qh, ql, Kb, g_k, kh, kl, MT);

        // join transpose, then attention
        cudaStreamWaitEvent(0, ev2, 0);
        attn_mma_kernel<<<dim3(BATCH * HEADS, TLEN / 128), 256, AT_SMEM>>>(
            qh, ql, kh, kl, vth, vtl, ah, al);

        o_gemm_kernel<<<dim3(8, MT / 128), 512, MM_SMEM>>>(ah, al, woh, wol, b_o, out);
    } else {
        convert_split3_kernel<<<dim3((DIM * DIM / 4) / 256, 3), 256>>>(
            W_q, W_k, W_o, wqh, wql, wkh, wkl, woh, wol);
        convert_split_kernel<<<(MT * DIM / 4) / 256, 256>>>(text, th, tl);
        rmsnorm_split_kernel<<<MN, 256>>>(features, g_feat, 1.0f, fh, fl);
        transpose_vt_kernel<<<dim3(NLEN / 32, HDIM / 32, BATCH * HEADS), dim3(32, 8)>>>(
            fh, fl, vth, vtl);
        qk_gemm_kernel<<<dim3(8, 96), 512, MM_SMEM>>>(
            th, tl, wqh, wql, b_q, Qb, fh, fl, wkh, wkl, b_k, Kb);
        rmsnorm_split2_kernel<<<MT + MN, 256>>>(Qb, g_q, qh, ql, Kb, g_k, kh, kl, MT);
        attn_mma_kernel<<<dim3(BATCH * HEADS, TLEN / 128), 256, AT_SMEM>>>(
            qh, ql, kh, kl, vth, vtl, ah, al);
        o_gemm_kernel<<<dim3(8, MT / 128), 512, MM_SMEM>>>(ah, al, woh, wol, b_o, out);
    }
}